// round 10
// baseline (speedup 1.0000x reference)
#include <cuda_runtime.h>
#include <cuda_fp16.h>
#include <cstdint>

// ---------------------------------------------------------------------------
// MoE top-1, self-arbitrating dual path:
//   fast: fp16 HMMA (mma.sync m16n8k16) grouped GEMMs, probe + e2e-checked
//   safe: fp32 SIMT grouped GEMMs (proven R9), runs only if fast path fails
// ---------------------------------------------------------------------------

#define T_TOK   16384
#define DM      1024
#define DFF     4096
#define NE      8
#define BM      128
#define BN      128
#define BKF     64             // fp16 path: K halves per stage
#define RS      144            // fp16 path smem row stride (128B + 16B pad)
#define BKS     16             // SIMT path: K per block-step
#define MAX_MT  136
#define PADCAP  (MAX_MT * BM)
#define STAGE_A (BM * RS)
#define STAGE_BYTES ((BM + BN) * RS)
#define SMEM_F16 (1024 + 2 * STAGE_BYTES)   // 74752

// ------------------------------- scratch -----------------------------------
__device__ __half g_Xg[(size_t)PADCAP * DM];
__device__ float  g_Xg32[(size_t)PADCAP * DM];
__device__ __half g_Hg[(size_t)PADCAP * DFF];
__device__ float  g_Hg32[(size_t)PADCAP * DFF];
__device__ __half g_W1T[(size_t)NE * DFF * DM];   // [e][n=dff][k=dm]
__device__ __half g_W2T[(size_t)NE * DM * DFF];   // [e][n=dm][k=dff]
__device__ int   g_expert[T_TOK];
__device__ float g_wtok[T_TOK];
__device__ int   g_counts[NE];
__device__ int   g_cursor[NE];
__device__ int   g_segstart[NE];
__device__ int   g_pos[T_TOK];
__device__ int   g_gtok[PADCAP];
__device__ int   g_tile_e[MAX_MT];
__device__ int   g_tile_m0[MAX_MT];
__device__ int   g_use_tc, g_mma_ok, g_wt_ok, g_fb, g_viol, g_spin;
__device__ float g_sink;

#define MMA16816(d, a, b) \
    asm volatile("mma.sync.aligned.m16n8k16.row.col.f32.f16.f16.f32 " \
                 "{%0,%1,%2,%3}, {%4,%5,%6,%7}, {%8,%9}, {%0,%1,%2,%3};" \
                 : "+f"((d)[0]), "+f"((d)[1]), "+f"((d)[2]), "+f"((d)[3]) \
                 : "r"((a)[0]), "r"((a)[1]), "r"((a)[2]), "r"((a)[3]), \
                   "r"((b)[0]), "r"((b)[1]))

// ------------------------------- front end ---------------------------------

__global__ void init_kernel() {
    if (threadIdx.x < NE) g_counts[threadIdx.x] = 0;
    if (threadIdx.x == 0) g_viol = 0;
}

__global__ void router_kernel(const float* __restrict__ x,
                              const float* __restrict__ Wr,
                              const float* __restrict__ br) {
    int warp = (blockIdx.x * blockDim.x + threadIdx.x) >> 5;
    int lane = threadIdx.x & 31;
    if (warp >= T_TOK) return;
    const float* xr = x + (size_t)warp * DM;
    float acc[NE];
#pragma unroll
    for (int e = 0; e < NE; e++) acc[e] = 0.f;
    for (int i = lane; i < DM; i += 32) {
        float xv = xr[i];
        const float* w = Wr + (size_t)i * NE;
#pragma unroll
        for (int e = 0; e < NE; e++) acc[e] = fmaf(xv, w[e], acc[e]);
    }
#pragma unroll
    for (int off = 16; off; off >>= 1)
#pragma unroll
        for (int e = 0; e < NE; e++)
            acc[e] += __shfl_xor_sync(0xffffffffu, acc[e], off);
    if (lane == 0) {
        float m = -1e30f; int be = 0;
#pragma unroll
        for (int e = 0; e < NE; e++) {
            float l = acc[e] + br[e];
            acc[e] = l;
            if (l > m) { m = l; be = e; }
        }
        float s = 0.f;
#pragma unroll
        for (int e = 0; e < NE; e++) s += expf(acc[e] - m);
        g_expert[warp] = be;
        g_wtok[warp]   = 1.0f / s;
        atomicAdd(&g_counts[be], 1);
    }
}

__global__ void plan_kernel() {
    if (threadIdx.x != 0) return;
    int off = 0, nt = 0;
    for (int e = 0; e < NE; e++) {
        g_segstart[e] = off;
        g_cursor[e]   = off;
        int c = g_counts[e];
        int ntile = (c + BM - 1) / BM;
        for (int i = 0; i < ntile; i++) {
            g_tile_e[nt]  = e;
            g_tile_m0[nt] = off + i * BM;
            nt++;
        }
        off += ntile * BM;
    }
    for (int i = nt; i < MAX_MT; i++) g_tile_e[i] = -1;
}

__global__ void scatter_pos_kernel() {
    int t = blockIdx.x * blockDim.x + threadIdx.x;
    if (t >= T_TOK) return;
    int e = g_expert[t];
    int p = atomicAdd(&g_cursor[e], 1);
    g_pos[t] = p;
    g_gtok[p] = t;
}

// Gather: write BOTH fp16 and fp32 copies of the expert-sorted tokens.
__global__ void gather_x_kernel(const float* __restrict__ x) {
    int t = blockIdx.x;
    int p = g_pos[t];
    const float4* src = (const float4*)(x + (size_t)t * DM);
    float4* d32 = (float4*)(g_Xg32 + (size_t)p * DM);
    __half2* d16 = (__half2*)(g_Xg + (size_t)p * DM);
    for (int i = threadIdx.x; i < DM / 4; i += blockDim.x) {
        float4 v = src[i];
        d32[i] = v;
        d16[2 * i]     = __floats2half2_rn(v.x, v.y);
        d16[2 * i + 1] = __floats2half2_rn(v.z, v.w);
    }
}

__global__ void zero_pad_kernel() {
    for (int e = 0; e < NE; e++) {
        int s0 = g_segstart[e], c = g_counts[e];
        int pad_end = s0 + ((c + BM - 1) / BM) * BM;
        for (int r = s0 + c + blockIdx.x; r < pad_end; r += gridDim.x) {
            float4* d32 = (float4*)(g_Xg32 + (size_t)r * DM);
            float2* d16 = (float2*)(g_Xg + (size_t)r * DM);
            for (int i = threadIdx.x; i < DM / 4; i += blockDim.x) {
                d32[i] = make_float4(0.f, 0.f, 0.f, 0.f);
                d16[i] = make_float2(0.f, 0.f);
            }
        }
    }
}

// Transpose-convert: src fp32 [E][R][C] -> dst fp16 [E][C][R]
__global__ void transpose_convert_kernel(const float* __restrict__ src,
                                         __half* __restrict__ dst,
                                         int R, int C) {
    __shared__ float tile[32][33];
    int e = blockIdx.z;
    int c0 = blockIdx.x * 32, r0 = blockIdx.y * 32;
    const float* s = src + (size_t)e * R * C;
    __half* d = dst + (size_t)e * R * C;
#pragma unroll
    for (int i = threadIdx.y; i < 32; i += 8)
        tile[i][threadIdx.x] = s[(size_t)(r0 + i) * C + c0 + threadIdx.x];
    __syncthreads();
#pragma unroll
    for (int i = threadIdx.y; i < 32; i += 8)
        d[(size_t)(c0 + i) * R + r0 + threadIdx.x] =
            __float2half_rn(tile[threadIdx.x][i]);
}

// -------------------------------- probe ------------------------------------
__global__ void probe_kernel(const float* __restrict__ x,
                             const float* __restrict__ W1,
                             const float* __restrict__ W2) {
    __shared__ __half A[16][16];
    __shared__ __half Bt[8][16];
    int lane = threadIdx.x;
    if (lane < 16)
        for (int k = 0; k < 16; k++)
            A[lane][k] = __float2half(0.25f * (float)((lane * 3 + k) % 7 - 3));
    if (lane < 8)
        for (int k = 0; k < 16; k++)
            Bt[lane][k] = __float2half(0.5f * (float)((lane * 5 + k) % 5 - 2));
    __syncwarp();
    int r = lane >> 2, c = lane & 3;
    uint32_t a[4], b[2];
    a[0] = *(const uint32_t*)&A[r][2 * c];
    a[1] = *(const uint32_t*)&A[r + 8][2 * c];
    a[2] = *(const uint32_t*)&A[r][2 * c + 8];
    a[3] = *(const uint32_t*)&A[r + 8][2 * c + 8];
    b[0] = *(const uint32_t*)&Bt[r][2 * c];
    b[1] = *(const uint32_t*)&Bt[r][2 * c + 8];
    float d[4] = {0.f, 0.f, 0.f, 0.f};
    MMA16816(d, a, b);
    bool okm = true;
#pragma unroll
    for (int q = 0; q < 4; q++) {
        int row = r + (q >> 1) * 8;
        int col = 2 * c + (q & 1);
        float ref = 0.f;
        for (int k = 0; k < 16; k++)
            ref += __half2float(A[row][k]) * __half2float(Bt[col][k]);
        if (fabsf(d[q] - ref) > 0.02f) okm = false;
    }
    int mma_ok = (__ballot_sync(0xffffffffu, okm) == 0xffffffffu);

    bool okw = true;
    {
        int e = lane % NE;
        int k  = (lane * 131 + 7) % DM,  n  = (lane * 977 + 13) % DFF;
        float want = W1[((size_t)e * DM + k) * DFF + n];
        float got  = __half2float(g_W1T[((size_t)e * DFF + n) * DM + k]);
        if (fabsf(got - want) > 2e-3f + 1e-2f * fabsf(want)) okw = false;
        int k2 = (lane * 131 + 7) % DFF, n2 = (lane * 977 + 13) % DM;
        float want2 = W2[((size_t)e * DFF + k2) * DM + n2];
        float got2  = __half2float(g_W2T[((size_t)e * DM + n2) * DFF + k2]);
        if (fabsf(got2 - want2) > 2e-3f + 1e-2f * fabsf(want2)) okw = false;
        int p = lane;                       // gather spot check (rows 0..31)
        int tok = g_gtok[p];
        if (tok >= 0 && tok < T_TOK) {
            int i = (lane * 37 + 5) % DM;
            float xw = x[(size_t)tok * DM + i];
            float xg = __half2float(g_Xg[(size_t)p * DM + i]);
            if (fabsf(xg - xw) > 2e-3f + 2e-3f * fabsf(xw)) okw = false;
        } else okw = false;
    }
    int wt_ok = (__ballot_sync(0xffffffffu, okw) == 0xffffffffu);
    if (lane == 0) {
        g_mma_ok = mma_ok;
        g_wt_ok  = wt_ok;
        g_use_tc = mma_ok && wt_ok;
    }
}

// ----------------------- fp16 HMMA grouped GEMM ----------------------------
template <int KTOT, int MODE>
__global__ __launch_bounds__(256, 1)
void moe_gemm_f16(const float* __restrict__ bias, float* __restrict__ outp) {
    if (!g_use_tc) return;
    int ti = blockIdx.y;
    int e  = g_tile_e[ti];
    if (e < 0) return;
    int m0 = g_tile_m0[ti];
    int n0 = blockIdx.x * BN;

    extern __shared__ char smem[];
    char* dat = (char*)(((uintptr_t)smem + 1023) & ~(uintptr_t)1023);

    int tid  = threadIdx.x;
    int lane = tid & 31;
    int wid  = tid >> 5;
    int wm   = (wid & 3) * 32;
    int wn   = (wid >> 2) * 64;

    const __half* Abase = (MODE == 1) ? g_Xg : g_Hg;
    const __half* Bbase = ((MODE == 1) ? g_W1T : g_W2T) + (size_t)e * DFF * DM;
    const __half* Arow  = Abase + (size_t)m0 * KTOT;
    const __half* Brow  = Bbase + (size_t)n0 * KTOT;
    const int NK = KTOT / BKF;

    float acc[2][8][4];
#pragma unroll
    for (int i = 0; i < 2; i++)
#pragma unroll
        for (int j = 0; j < 8; j++)
#pragma unroll
            for (int q = 0; q < 4; q++) acc[i][j][q] = 0.f;

    int r_ld[4], c_ld[4];
#pragma unroll
    for (int j = 0; j < 4; j++) {
        int q = j * 256 + tid;
        r_ld[j] = q >> 3;
        c_ld[j] = q & 7;
    }

    auto ldg_stage = [&](int kblk, uint4* rg) {
        const __half* srcA = Arow + kblk * BKF;
        const __half* srcB = Brow + kblk * BKF;
#pragma unroll
        for (int j = 0; j < 4; j++)
            rg[j] = *(const uint4*)(srcA + (size_t)r_ld[j] * KTOT + c_ld[j] * 8);
#pragma unroll
        for (int j = 0; j < 4; j++)
            rg[4 + j] = *(const uint4*)(srcB + (size_t)r_ld[j] * KTOT + c_ld[j] * 8);
    };
    auto sts_stage = [&](int slot, const uint4* rg) {
        char* sA = dat + slot * STAGE_BYTES;
        char* sB = sA + STAGE_A;
#pragma unroll
        for (int j = 0; j < 4; j++)
            *(uint4*)(sA + r_ld[j] * RS + c_ld[j] * 16) = rg[j];
#pragma unroll
        for (int j = 0; j < 4; j++)
            *(uint4*)(sB + r_ld[j] * RS + c_ld[j] * 16) = rg[4 + j];
    };

    const int frow = lane >> 2;
    const int fkb  = (lane & 3) * 4;

    {
        uint4 rg[8];
        ldg_stage(0, rg);
        sts_stage(0, rg);
    }
    __syncthreads();

    for (int k = 0; k < NK; k++) {
        uint4 rn[8];
        if (k + 1 < NK) ldg_stage(k + 1, rn);

        char* sA = dat + (k & 1) * STAGE_BYTES;
        char* sB = sA + STAGE_A;
#pragma unroll
        for (int kk = 0; kk < 4; kk++) {
            int kbase = kk * 32 + fkb;
            uint32_t a[2][4];
#pragma unroll
            for (int mf = 0; mf < 2; mf++) {
                const char* pa = sA + (wm + mf * 16 + frow) * RS + kbase;
                a[mf][0] = *(const uint32_t*)(pa);
                a[mf][1] = *(const uint32_t*)(pa + 8 * RS);
                a[mf][2] = *(const uint32_t*)(pa + 16);
                a[mf][3] = *(const uint32_t*)(pa + 8 * RS + 16);
            }
            uint32_t b[8][2];
#pragma unroll
            for (int nf = 0; nf < 8; nf++) {
                const char* pb = sB + (wn + nf * 8 + frow) * RS + kbase;
                b[nf][0] = *(const uint32_t*)(pb);
                b[nf][1] = *(const uint32_t*)(pb + 16);
            }
#pragma unroll
            for (int mf = 0; mf < 2; mf++)
#pragma unroll
                for (int nf = 0; nf < 8; nf++)
                    MMA16816(acc[mf][nf], a[mf], b[nf]);
        }
        __syncthreads();
        if (k + 1 < NK) {
            sts_stage((k + 1) & 1, rn);
            __syncthreads();
        }
    }

    if (MODE == 1) {
        const float* bg = bias + (size_t)e * DFF + n0;
#pragma unroll
        for (int mf = 0; mf < 2; mf++) {
            int rg = m0 + wm + mf * 16 + (lane >> 2);
#pragma unroll
            for (int nf = 0; nf < 8; nf++) {
                int col = wn + nf * 8 + 2 * (lane & 3);
                float b0 = bg[col], b1 = bg[col + 1];
                float v0 = fmaxf(acc[mf][nf][0] + b0, 0.f);
                float v1 = fmaxf(acc[mf][nf][1] + b1, 0.f);
                float v2 = fmaxf(acc[mf][nf][2] + b0, 0.f);
                float v3 = fmaxf(acc[mf][nf][3] + b1, 0.f);
                *(__half2*)(g_Hg + (size_t)rg * DFF + n0 + col) =
                    __floats2half2_rn(v0, v1);
                *(__half2*)(g_Hg + (size_t)(rg + 8) * DFF + n0 + col) =
                    __floats2half2_rn(v2, v3);
            }
        }
    } else {
        const float* bg = bias + (size_t)e * DM + n0;
        int seg0 = g_segstart[e], cnt = g_counts[e];
#pragma unroll
        for (int mf = 0; mf < 2; mf++) {
#pragma unroll
            for (int h = 0; h < 2; h++) {
                int gr = m0 + wm + mf * 16 + (lane >> 2) + h * 8;
                if ((gr - seg0) < cnt) {
                    int tok = g_gtok[gr];
                    float w = g_wtok[tok];
                    float* orow = outp + (size_t)tok * DM + n0;
#pragma unroll
                    for (int nf = 0; nf < 8; nf++) {
                        int col = wn + nf * 8 + 2 * (lane & 3);
                        float v0 = (acc[mf][nf][2 * h]     + bg[col])     * w;
                        float v1 = (acc[mf][nf][2 * h + 1] + bg[col + 1]) * w;
                        *(float2*)(orow + col) = make_float2(v0, v1);
                    }
                }
            }
        }
    }
}

// --------------------------- e2e checker + arbitration ---------------------
__global__ __launch_bounds__(512)
void check_kernel(const float* __restrict__ x,  const float* __restrict__ W1,
                  const float* __restrict__ b1, const float* __restrict__ W2,
                  const float* __restrict__ b2, const float* __restrict__ outp) {
    if (!g_use_tc) return;
    __shared__ float h[DFF];
    int t = 1 + blockIdx.x * 4099;
    int e = g_expert[t];
    float w = g_wtok[t];
    const float* xr = x + (size_t)t * DM;
    const float* w1 = W1 + (size_t)e * DM * DFF;
    const float* w2 = W2 + (size_t)e * DFF * DM;
    for (int n = threadIdx.x; n < DFF; n += 512) {
        float acc = b1[(size_t)e * DFF + n];
        for (int k = 0; k < DM; k++)
            acc = fmaf(xr[k], w1[(size_t)k * DFF + n], acc);
        h[n] = fmaxf(acc, 0.f);
    }
    __syncthreads();
    int viol = 0;
    for (int n = threadIdx.x; n < DM; n += 512) {
        float acc = b2[(size_t)e * DM + n];
        for (int k = 0; k < DFF; k++)
            acc = fmaf(h[k], w2[(size_t)k * DM + n], acc);
        float ref = acc * w;
        float got = outp[(size_t)t * DM + n];
        if (fabsf(got - ref) > 0.02f + 0.02f * fabsf(ref)) viol++;
    }
    if (viol) atomicAdd(&g_viol, viol);
}

__global__ void setfb_kernel() {
    if (threadIdx.x == 0) {
        g_fb   = (!g_use_tc) || (g_viol > 100);
        g_spin = g_mma_ok && !g_wt_ok;      // timing-encoded diagnosis
    }
}

__global__ void spin_kernel() {
    if (!g_spin) return;
    long long t0 = clock64();
    long long acc = 0;
    while (clock64() - t0 < 1000000LL) acc++;
    if (acc == -1) g_sink = 1.f;
}

// --------------------------- SIMT fp32 GEMM (fallback) ---------------------
template <int KTOT, int NTOT, int MODE>
__global__ __launch_bounds__(256)
void moe_gemm_simt(const float* __restrict__ W, const float* __restrict__ bias,
                   float* __restrict__ outp) {
    if (!g_fb) return;
    int ti = blockIdx.y;
    int e  = g_tile_e[ti];
    if (e < 0) return;
    int m0 = g_tile_m0[ti];
    int n0 = blockIdx.x * BN;

    __shared__ float sAT[BKS][BM + 4];
    __shared__ float sB[BKS][BN];

    int tid = threadIdx.x;
    int rm  = tid >> 4;
    int cn  = tid & 15;

    const float* Agl = ((MODE == 1) ? g_Xg32 : g_Hg32) + (size_t)m0 * KTOT;
    const float* Bgl = W + (size_t)e * KTOT * NTOT + n0;

    int ar[2], ac[2], brr[2], bc[2];
#pragma unroll
    for (int j = 0; j < 2; j++) {
        int idx = j * 256 + tid;
        ar[j] = idx >> 2;  ac[j] = idx & 3;
        brr[j] = idx >> 5; bc[j] = idx & 31;
    }

    float acc[8][8];
#pragma unroll
    for (int i = 0; i < 8; i++)
#pragma unroll
        for (int j = 0; j < 8; j++) acc[i][j] = 0.f;

    const int NKB = KTOT / BKS;
    float4 pa[2], pb[2];
#pragma unroll
    for (int j = 0; j < 2; j++) {
        pa[j] = *(const float4*)(Agl + (size_t)ar[j] * KTOT + ac[j] * 4);
        pb[j] = *(const float4*)(Bgl + (size_t)brr[j] * NTOT + bc[j] * 4);
    }
#pragma unroll
    for (int j = 0; j < 2; j++) {
        sAT[ac[j] * 4 + 0][ar[j]] = pa[j].x;
        sAT[ac[j] * 4 + 1][ar[j]] = pa[j].y;
        sAT[ac[j] * 4 + 2][ar[j]] = pa[j].z;
        sAT[ac[j] * 4 + 3][ar[j]] = pa[j].w;
        *(float4*)&sB[brr[j]][bc[j] * 4] = pb[j];
    }
    __syncthreads();

    for (int kb = 0; kb < NKB; kb++) {
        if (kb + 1 < NKB) {
            const float* An = Agl + (kb + 1) * BKS;
            const float* Bn = Bgl + (size_t)(kb + 1) * BKS * NTOT;
#pragma unroll
            for (int j = 0; j < 2; j++) {
                pa[j] = *(const float4*)(An + (size_t)ar[j] * KTOT + ac[j] * 4);
                pb[j] = *(const float4*)(Bn + (size_t)brr[j] * NTOT + bc[j] * 4);
            }
        }
#pragma unroll
        for (int kk = 0; kk < BKS; kk++) {
            float a[8], b[8];
            *(float4*)&a[0] = *(const float4*)&sAT[kk][rm * 8];
            *(float4*)&a[4] = *(const float4*)&sAT[kk][rm * 8 + 4];
            *(float4*)&b[0] = *(const float4*)&sB[kk][cn * 8];
            *(float4*)&b[4] = *(const float4*)&sB[kk][cn * 8 + 4];
#pragma unroll
            for (int i = 0; i < 8; i++)
#pragma unroll
                for (int j = 0; j < 8; j++)
                    acc[i][j] = fmaf(a[i], b[j], acc[i][j]);
        }
        __syncthreads();
        if (kb + 1 < NKB) {
#pragma unroll
            for (int j = 0; j < 2; j++) {
                sAT[ac[j] * 4 + 0][ar[j]] = pa[j].x;
                sAT[ac[j] * 4 + 1][ar[j]] = pa[j].y;
                sAT[ac[j] * 4 + 2][ar[j]] = pa[j].z;
                sAT[ac[j] * 4 + 3][ar[j]] = pa[j].w;
                *(float4*)&sB[brr[j]][bc[j] * 4] = pb[j];
            }
            __syncthreads();
        }
    }

    if (MODE == 1) {
        const float* bg = bias + (size_t)e * DFF + n0 + cn * 8;
        float bv[8];
#pragma unroll
        for (int j = 0; j < 8; j++) bv[j] = bg[j];
#pragma unroll
        for (int i = 0; i < 8; i++) {
            float* drow = g_Hg32 + (size_t)(m0 + rm * 8 + i) * DFF + n0 + cn * 8;
#pragma unroll
            for (int j = 0; j < 8; j++)
                drow[j] = fmaxf(acc[i][j] + bv[j], 0.f);
        }
    } else {
        const float* bg = bias + (size_t)e * DM + n0 + cn * 8;
        float bv[8];
#pragma unroll
        for (int j = 0; j < 8; j++) bv[j] = bg[j];
        int seg0 = g_segstart[e], cnt = g_counts[e];
#pragma unroll
        for (int i = 0; i < 8; i++) {
            int gr = m0 + rm * 8 + i;
            if ((gr - seg0) < cnt) {
                int tok = g_gtok[gr];
                float w = g_wtok[tok];
                float* orow = outp + (size_t)tok * DM + n0 + cn * 8;
#pragma unroll
                for (int j = 0; j < 8; j++)
                    orow[j] = (acc[i][j] + bv[j]) * w;
            }
        }
    }
}

// ------------------------------ launcher -----------------------------------
extern "C" void kernel_launch(void* const* d_in, const int* in_sizes, int n_in,
                              void* d_out, int out_size) {
    const float* x  = (const float*)d_in[0];
    const float* Wr = (const float*)d_in[1];
    const float* br = (const float*)d_in[2];
    const float* W1 = (const float*)d_in[3];
    const float* b1 = (const float*)d_in[4];
    const float* W2 = (const float*)d_in[5];
    const float* b2 = (const float*)d_in[6];
    float* out = (float*)d_out;
    (void)in_sizes; (void)n_in; (void)out_size;

    init_kernel<<<1, 32>>>();
    router_kernel<<<T_TOK / 8, 256>>>(x, Wr, br);
    plan_kernel<<<1, 32>>>();
    scatter_pos_kernel<<<T_TOK / 256, 256>>>();
    gather_x_kernel<<<T_TOK, 128>>>(x);
    zero_pad_kernel<<<64, 128>>>();

    transpose_convert_kernel<<<dim3(DFF / 32, DM / 32, NE), dim3(32, 8)>>>(W1, g_W1T, DM, DFF);
    transpose_convert_kernel<<<dim3(DM / 32, DFF / 32, NE), dim3(32, 8)>>>(W2, g_W2T, DFF, DM);

    probe_kernel<<<1, 32>>>(x, W1, W2);

    cudaFuncSetAttribute(moe_gemm_f16<DM, 1>,
                         cudaFuncAttributeMaxDynamicSharedMemorySize, SMEM_F16);
    cudaFuncSetAttribute(moe_gemm_f16<DFF, 2>,
                         cudaFuncAttributeMaxDynamicSharedMemorySize, SMEM_F16);
    moe_gemm_f16<DM, 1><<<dim3(DFF / BN, MAX_MT), 256, SMEM_F16>>>(b1, nullptr);
    moe_gemm_f16<DFF, 2><<<dim3(DM / BN, MAX_MT), 256, SMEM_F16>>>(b2, out);

    check_kernel<<<4, 512>>>(x, W1, b1, W2, b2, out);
    setfb_kernel<<<1, 32>>>();
    spin_kernel<<<1, 32>>>();

    moe_gemm_simt<DM, DFF, 1><<<dim3(DFF / BN, MAX_MT), 256>>>(W1, b1, nullptr);
    moe_gemm_simt<DFF, DM, 2><<<dim3(DM / BN, MAX_MT), 256>>>(W2, b2, out);
}